// round 9
// baseline (speedup 1.0000x reference)
#include <cuda_runtime.h>
#include <cstdint>
#include <math.h>

#define EPS 1e-9f

#define BATCH   64
#define HW1     64
#define HW2     28
#define NROUTES 6272
#define NCAPS   10
#define ODIM    16
#define JDIM    8

#define RBLOCKS 784
#define NPER    8        // n's per route block
#define NREP    8        // s-accumulator replicas

typedef unsigned long long u64;
typedef unsigned int       u32;

__device__ float g_h[(size_t)BATCH*64*HW1*HW1];      // conv1 out [b][ic][ih][iw]
__device__ float g_wT[64*81*64];                     // conv2 weights [ic][q][slot]
__device__ float g_u[(size_t)NROUTES*BATCH*JDIM];    // primary caps [n][b][8]
__device__ float g_v[BATCH*NCAPS*ODIM];              // v0, then v0+v1
__device__ float g_sR[NREP*BATCH*NCAPS*ODIM];        // replicated s accumulators

// ---------- packed fp32x2 helpers ----------
__device__ __forceinline__ u64 pack2(float x) {
    u64 r; asm("mov.b64 %0, {%1, %1};" : "=l"(r) : "f"(x)); return r;
}
__device__ __forceinline__ u64 packpair(float lo, float hi) {
    u64 r; asm("mov.b64 %0, {%1, %2};" : "=l"(r) : "f"(lo), "f"(hi)); return r;
}
__device__ __forceinline__ void ffma2(u64& d, u64 a, u64 b) {
    asm("fma.rn.f32x2 %0, %1, %2, %0;" : "+l"(d) : "l"(a), "l"(b));
}
__device__ __forceinline__ float2 unpack2(u64 a) {
    float2 f; asm("mov.b64 {%0, %1}, %2;" : "=f"(f.x), "=f"(f.y) : "l"(a)); return f;
}
// ---------- cp.async helpers ----------
__device__ __forceinline__ void cpasync16(u32 saddr, const void* gaddr) {
    asm volatile("cp.async.cg.shared.global [%0], [%1], 16;" :: "r"(saddr), "l"(gaddr));
}
__device__ __forceinline__ void cpcommit() {
    asm volatile("cp.async.commit_group;");
}
__device__ __forceinline__ void cpwait0() {
    asm volatile("cp.async.wait_group 0;");
}

// ============================================================
// one-time weight transpose for conv2:
// g_wT[ic][q][slot], slot = grp*4 + (c7&3) + (c7>=4 ? 32 : 0)
// ============================================================
__global__ __launch_bounds__(256) void w_transform_kernel(const float* __restrict__ w)
{
    int idx = blockIdx.x*256 + threadIdx.x;            // = oc*5184 + ic*81 + q
    if (idx >= 64*64*81) return;
    int oc  = idx / 5184;
    int rem = idx - oc*5184;
    int ic  = rem / 81;
    int q   = rem - ic*81;
    int c7  = oc & 7, grp = oc >> 3;
    int slot = grp*4 + (c7 & 3) + ((c7 >= 4) ? 32 : 0);
    g_wT[(size_t)ic*5184 + q*64 + slot] = w[idx];
}

// ============================================================
// conv1: (64,1,64,64) -> (64,64,64,64), k5 pad2 + bias + relu
// f32x2 over oc-pairs: 32 pairs x 25 taps FFMA2 per thread
// ============================================================
__global__ __launch_bounds__(256) void conv1_kernel(
    const float* __restrict__ x, const float* __restrict__ w,
    const float* __restrict__ bias)
{
    __shared__ float xs[20][20];
    __shared__ u64 ws2[25*32];     // [k][pair]
    __shared__ float bs[64];
    int b   = blockIdx.z;
    int ty0 = blockIdx.y * 16, tx0 = blockIdx.x * 16;
    int tid = threadIdx.y * 16 + threadIdx.x;

    for (int i = tid; i < 25*32; i += 256) {
        int k = i >> 5, p = i & 31;
        ws2[i] = packpair(w[(2*p)*25 + k], w[(2*p+1)*25 + k]);
    }
    if (tid < 64) bs[tid] = bias[tid];

    const float* xb = x + (size_t)b * HW1 * HW1;
    for (int i = tid; i < 400; i += 256) {
        int r = i / 20, c = i % 20;
        int gy = ty0 + r - 2, gx = tx0 + c - 2;
        float v = 0.f;
        if (gy >= 0 && gy < HW1 && gx >= 0 && gx < HW1) v = xb[gy*HW1 + gx];
        xs[r][c] = v;
    }
    __syncthreads();

    int ty = threadIdx.y, tx = threadIdx.x;
    u64 in2[25];
#pragma unroll
    for (int kh = 0; kh < 5; kh++)
#pragma unroll
        for (int kw = 0; kw < 5; kw++)
            in2[kh*5+kw] = pack2(xs[ty+kh][tx+kw]);

    int y = ty0 + ty, xc = tx0 + tx;
    float* hout = g_h + ((size_t)b*64)*HW1*HW1 + y*HW1 + xc;
#pragma unroll 4
    for (int p = 0; p < 32; p++) {
        u64 acc = packpair(bs[2*p], bs[2*p+1]);
#pragma unroll
        for (int k = 0; k < 25; k++) ffma2(acc, in2[k], ws2[k*32 + p]);
        float2 f = unpack2(acc);
        hout[(size_t)(2*p)*HW1*HW1]   = fmaxf(f.x, 0.f);
        hout[(size_t)(2*p+1)*HW1*HW1] = fmaxf(f.y, 0.f);
    }
}

// ============================================================
// conv2: k9 s2 + bias + capsule squash -> g_u[n][b][8]
// cp.async double-buffered staging; 4-row micro-tile.
// grid (7, 64) x 224 threads. (fp32 FFMA2 roofline ~500us)
// ============================================================
#define C2_WSZ 5184          // 81*64
#define C2_ISZ 960           // 15*64
#define C2_SMEM ((2*C2_WSZ + 2*C2_ISZ)*4)

__global__ __launch_bounds__(224) void conv2_kernel(const float* __restrict__ bias)
{
    extern __shared__ float dsm[];
    float* wsd = dsm;                 // [2][5184]
    float* ins = dsm + 2*C2_WSZ;      // [2][960]

    int b   = blockIdx.y;
    int t   = blockIdx.x;              // 0..6 -> output rows 4t..4t+3
    int tid = threadIdx.x;
    int ocg = tid & 7;
    int ow  = tid >> 3;
    int ow2 = ow * 2;

    u32 s_wsd = (u32)__cvta_generic_to_shared(wsd);
    u32 s_ins = (u32)__cvta_generic_to_shared(ins);

    const float* hb = g_h + (size_t)b*64*HW1*HW1 + (size_t)(8*t)*HW1;

    auto stage = [&](int ic, int buf) {
        u32 sw = s_wsd + buf*(C2_WSZ*4);
        u32 si = s_ins + buf*(C2_ISZ*4);
        const float* wsrc = g_wT + (size_t)ic*C2_WSZ;
        const float* isrc = hb + (size_t)ic*HW1*HW1;
#pragma unroll
        for (int k = 0; k < 6; k++) {
            int i = tid + k*224;
            if (i < 1296) cpasync16(sw + i*16, wsrc + i*4);
        }
#pragma unroll
        for (int k = 0; k < 2; k++) {
            int i = tid + k*224;
            if (i < 240) cpasync16(si + i*16, isrc + i*4);
        }
    };

    u64 acc[4][4];
#pragma unroll
    for (int r = 0; r < 4; r++)
#pragma unroll
        for (int k = 0; k < 4; k++) acc[r][k] = 0ull;

    stage(0, 0); cpcommit();

    for (int ic = 0; ic < 64; ic++) {
        int buf = ic & 1;
        cpwait0();
        __syncthreads();
        if (ic + 1 < 64) { stage(ic+1, buf ^ 1); cpcommit(); }

        const float* wb_ = wsd + buf*C2_WSZ;
        const float* ib_ = ins + buf*C2_ISZ;
#pragma unroll
        for (int kh = 0; kh < 9; kh++) {
#pragma unroll
            for (int kw = 0; kw < 9; kw++) {
                int q = kh*9 + kw;
                const u64* WA = (const u64*)&wb_[q*64 + ocg*4];
                const u64* WB = (const u64*)&wb_[q*64 + 32 + ocg*4];
                u64 wa0 = WA[0], wa1 = WA[1];
                u64 wb0 = WB[0], wb1 = WB[1];
#pragma unroll
                for (int r = 0; r < 4; r++) {
                    u64 iv = pack2(ib_[(kh + 2*r)*64 + ow2 + kw]);
                    ffma2(acc[r][0], iv, wa0); ffma2(acc[r][1], iv, wa1);
                    ffma2(acc[r][2], iv, wb0); ffma2(acc[r][3], iv, wb1);
                }
            }
        }
    }

    float bvals[8];
#pragma unroll
    for (int c = 0; c < 8; c++) bvals[c] = bias[ocg*8 + c];

#pragma unroll
    for (int r = 0; r < 4; r++) {
        float a[8];
#pragma unroll
        for (int k = 0; k < 4; k++) {
            float2 f = unpack2(acc[r][k]);
            a[2*k]   = f.x + bvals[2*k];
            a[2*k+1] = f.y + bvals[2*k+1];
        }
        float msq = 0.f;
#pragma unroll
        for (int c = 0; c < 8; c++) msq = fmaf(a[c], a[c], msq);
        float mag   = sqrtf(msq + EPS);
        float scale = msq / (1.f + msq) / (mag + EPS);
        int n = ocg*(HW2*HW2) + (4*t + r)*HW2 + ow;
        float* up = g_u + ((size_t)n*BATCH + b)*JDIM;   // [n][b][8]
        *(float4*)up       = make_float4(a[0]*scale, a[1]*scale, a[2]*scale, a[3]*scale);
        *(float4*)(up + 4) = make_float4(a[4]*scale, a[5]*scale, a[6]*scale, a[7]*scale);
    }
}

// ============================================================
// routing sweep: 320 threads (warp = o, lane = bb), grid (784,2)
// NPER=8, all W+u staged once via cp.async; u in split float4
// arrays (lane-contiguous -> conflict-free). 2 blocks/SM.
// iter0 sync-free; iter>=1 one sync per n (parity dbl-buf ex).
// ============================================================
#define R_WS   (NPER*1280)         // 10240 floats
#define R_USA  (NPER*32*4)         // 1024 floats
#define R_USB  (NPER*32*4)         // 1024 floats
#define R_EX   (2*NCAPS*32)        // 640 floats
#define R_SMEM ((R_WS + R_USA + R_USB + R_EX)*4)

__global__ __launch_bounds__(320, 2) void route_kernel(
    const float* __restrict__ W, int iter)
{
    extern __shared__ float dsm[];
    float* Ws  = dsm;                          // [8][1280]
    float* usA = dsm + R_WS;                   // [8][32] float4
    float* usB = dsm + R_WS + R_USA;           // [8][32] float4
    float* ex  = dsm + R_WS + R_USA + R_USB;   // [2][10][32]

    int tid  = threadIdx.x;          // 0..319
    int o    = tid >> 5;             // warp = capsule o
    int lane = tid & 31;
    int h    = blockIdx.y;           // bb half
    int bb   = h*32 + lane;
    int n0   = blockIdx.x * NPER;

    u32 s_ws  = (u32)__cvta_generic_to_shared(Ws);
    u32 s_usA = (u32)__cvta_generic_to_shared(usA);
    u32 s_usB = (u32)__cvta_generic_to_shared(usB);

    // stage all W: 2560 chunks = exactly 8 * 320
    const float* wsrc = W + (size_t)n0*1280;
#pragma unroll
    for (int k = 0; k < 8; k++) {
        int i = tid + k*320;
        cpasync16(s_ws + i*16, wsrc + (size_t)i*4);
    }
    // stage all u for this bb-half: 512 chunks into split A/B arrays
#pragma unroll
    for (int k = 0; k < 2; k++) {
        int i = tid + k*320;
        if (i < 512) {
            int nn   = i >> 6;
            int rem  = i & 63;
            int half = rem >> 5;
            int ll   = rem & 31;
            u32 dst  = (half ? s_usB : s_usA) + (nn*32 + ll)*16;
            const float* usrc = g_u + ((size_t)(n0+nn)*BATCH + h*32 + ll)*JDIM + half*4;
            cpasync16(dst, usrc);
        }
    }
    cpcommit();

    float v[16];
    if (iter > 0) {
        const float4* vp = (const float4*)(g_v + (bb*NCAPS + o)*ODIM);
#pragma unroll
        for (int k = 0; k < 4; k++) {
            float4 f = vp[k];
            v[4*k] = f.x; v[4*k+1] = f.y; v[4*k+2] = f.z; v[4*k+3] = f.w;
        }
    }

    float acc[16];
#pragma unroll
    for (int i = 0; i < 16; i++) acc[i] = 0.f;

    cpwait0();
    __syncthreads();

    for (int nn = 0; nn < NPER; nn++) {
        float4 ua = ((const float4*)usA)[nn*32 + lane];
        float4 ub = ((const float4*)usB)[nn*32 + lane];

        float uh[16];
        const float* wrow = Ws + nn*1280 + o*128;   // warp-uniform -> broadcast
#pragma unroll
        for (int i = 0; i < 16; i++) {
            float4 wa = *(const float4*)(wrow + i*8);
            float4 wb = *(const float4*)(wrow + i*8 + 4);
            float s = wa.x * ua.x;
            s = fmaf(wa.y, ua.y, s); s = fmaf(wa.z, ua.z, s); s = fmaf(wa.w, ua.w, s);
            s = fmaf(wb.x, ub.x, s); s = fmaf(wb.y, ub.y, s);
            s = fmaf(wb.z, ub.z, s); s = fmaf(wb.w, ub.w, s);
            uh[i] = s;
        }

        float c;
        if (iter == 0) {
            c = 0.1f;
        } else {
            float bnew = 0.f;
#pragma unroll
            for (int i = 0; i < 16; i++) bnew = fmaf(uh[i], v[i], bnew);
            float e = __expf(bnew);
            int par = nn & 1;
            ex[(par*NCAPS + o)*32 + lane] = e;
            __syncthreads();            // parity dbl-buf protects reuse
            float denom = 0.f;
#pragma unroll
            for (int k = 0; k < 10; k++) denom += ex[(par*NCAPS + k)*32 + lane];
            c = __fdividef(e, denom);
        }
#pragma unroll
        for (int i = 0; i < 16; i++) acc[i] = fmaf(c, uh[i], acc[i]);
    }

    int rep = (blockIdx.x*2 + blockIdx.y) & (NREP-1);
    float* sp = g_sR + rep*(BATCH*NCAPS*ODIM) + (bb*NCAPS + o)*ODIM;
#pragma unroll
    for (int i = 0; i < 16; i++) atomicAdd(&sp[i], acc[i]);
}

// ============================================================
// sum 8 replicas, squash -> v / out; re-zero replicas.
// mode 0: g_v = v0 ; mode 1: g_v += v1 ; mode 2: write out
// ============================================================
__global__ __launch_bounds__(256) void squash_v_kernel(float* __restrict__ out, int mode)
{
    int tid  = blockIdx.x*256 + threadIdx.x;
    int boq  = tid >> 2;
    int quad = tid & 3;

    float4 s = make_float4(0.f, 0.f, 0.f, 0.f);
#pragma unroll
    for (int r = 0; r < NREP; r++) {
        float* p = g_sR + r*(BATCH*NCAPS*ODIM) + boq*ODIM + quad*4;
        float4 t = *(const float4*)p;
        *(float4*)p = make_float4(0.f, 0.f, 0.f, 0.f);
        s.x += t.x; s.y += t.y; s.z += t.z; s.w += t.w;
    }

    float part = s.x*s.x + s.y*s.y + s.z*s.z + s.w*s.w;
    part += __shfl_xor_sync(0xffffffff, part, 1);
    part += __shfl_xor_sync(0xffffffff, part, 2);
    float msq   = part;
    float mag   = sqrtf(msq + EPS);
    float scale = msq / (1.f + msq) / (mag + EPS);
    float4 vv = make_float4(s.x*scale, s.y*scale, s.z*scale, s.w*scale);

    if (mode == 0) {
        *(float4*)(g_v + boq*ODIM + quad*4) = vv;
    } else if (mode == 1) {
        float4 old = *(const float4*)(g_v + boq*ODIM + quad*4);
        old.x += vv.x; old.y += vv.y; old.z += vv.z; old.w += vv.w;
        *(float4*)(g_v + boq*ODIM + quad*4) = old;
    } else {
        *(float4*)(out + boq*ODIM + quad*4) = vv;
    }
}

// ============================================================
extern "C" void kernel_launch(void* const* d_in, const int* in_sizes, int n_in,
                              void* d_out, int out_size)
{
    const float* x   = (const float*)d_in[0];
    const float* c1w = (const float*)d_in[1];
    const float* c1b = (const float*)d_in[2];
    const float* pw  = (const float*)d_in[3];
    const float* pb  = (const float*)d_in[4];
    const float* W   = (const float*)d_in[5];
    float* out = (float*)d_out;

    static int attr_done = 0;
    if (!attr_done) {
        cudaFuncSetAttribute(conv2_kernel, cudaFuncAttributeMaxDynamicSharedMemorySize, C2_SMEM);
        cudaFuncSetAttribute(route_kernel, cudaFuncAttributeMaxDynamicSharedMemorySize, R_SMEM);
        attr_done = 1;
    }

    w_transform_kernel<<<(64*64*81 + 255)/256, 256>>>(pw);
    conv1_kernel<<<dim3(4,4,64), dim3(16,16)>>>(x, c1w, c1b);
    conv2_kernel<<<dim3(7,64), 224, C2_SMEM>>>(pb);

    route_kernel<<<dim3(RBLOCKS,2), 320, R_SMEM>>>(W, 0);
    squash_v_kernel<<<10, 256>>>(out, 0);
    route_kernel<<<dim3(RBLOCKS,2), 320, R_SMEM>>>(W, 1);
    squash_v_kernel<<<10, 256>>>(out, 1);
    route_kernel<<<dim3(RBLOCKS,2), 320, R_SMEM>>>(W, 2);
    squash_v_kernel<<<10, 256>>>(out, 2);
}

// round 10
// speedup vs baseline: 1.1230x; 1.1230x over previous
#include <cuda_runtime.h>
#include <cstdint>
#include <math.h>

#define EPS 1e-9f

#define BATCH   64
#define HW1     64
#define HW2     28
#define NROUTES 6272
#define NCAPS   10
#define ODIM    16
#define JDIM    8

#define RBLOCKS 392
#define NPER    16       // n's per route block
#define NREP    8        // s-accumulator replicas

typedef unsigned long long u64;
typedef unsigned int       u32;

__device__ float g_h[(size_t)BATCH*64*HW1*HW1];      // conv1 out [b][ic][ih][iw]
__device__ float g_wT[64*81*64];                     // conv2 weights [ic][q][slot]
__device__ float g_u[(size_t)NROUTES*BATCH*JDIM];    // primary caps [n][b][8]
__device__ float g_v[BATCH*NCAPS*ODIM];              // v0, then v0+v1
__device__ float g_sR[NREP*BATCH*NCAPS*ODIM];        // replicated s accumulators

// ---------- packed fp32x2 helpers ----------
__device__ __forceinline__ u64 pack2(float x) {
    u64 r; asm("mov.b64 %0, {%1, %1};" : "=l"(r) : "f"(x)); return r;
}
__device__ __forceinline__ u64 packpair(float lo, float hi) {
    u64 r; asm("mov.b64 %0, {%1, %2};" : "=l"(r) : "f"(lo), "f"(hi)); return r;
}
__device__ __forceinline__ void ffma2(u64& d, u64 a, u64 b) {
    asm("fma.rn.f32x2 %0, %1, %2, %0;" : "+l"(d) : "l"(a), "l"(b));
}
__device__ __forceinline__ float2 unpack2(u64 a) {
    float2 f; asm("mov.b64 {%0, %1}, %2;" : "=f"(f.x), "=f"(f.y) : "l"(a)); return f;
}
// ---------- cp.async helpers ----------
__device__ __forceinline__ void cpasync16(u32 saddr, const void* gaddr) {
    asm volatile("cp.async.cg.shared.global [%0], [%1], 16;" :: "r"(saddr), "l"(gaddr));
}
__device__ __forceinline__ void cpcommit() {
    asm volatile("cp.async.commit_group;");
}
__device__ __forceinline__ void cpwait0() {
    asm volatile("cp.async.wait_group 0;");
}

// ============================================================
// one-time weight transpose for conv2:
// g_wT[ic][q][slot], slot = grp*4 + (c7&3) + (c7>=4 ? 32 : 0)
// ============================================================
__global__ __launch_bounds__(256) void w_transform_kernel(const float* __restrict__ w)
{
    int idx = blockIdx.x*256 + threadIdx.x;            // = oc*5184 + ic*81 + q
    if (idx >= 64*64*81) return;
    int oc  = idx / 5184;
    int rem = idx - oc*5184;
    int ic  = rem / 81;
    int q   = rem - ic*81;
    int c7  = oc & 7, grp = oc >> 3;
    int slot = grp*4 + (c7 & 3) + ((c7 >= 4) ? 32 : 0);
    g_wT[(size_t)ic*5184 + q*64 + slot] = w[idx];
}

// ============================================================
// conv1: (64,1,64,64) -> (64,64,64,64), k5 pad2 + bias + relu
// f32x2 over oc-pairs: 32 pairs x 25 taps FFMA2 per thread
// ============================================================
__global__ __launch_bounds__(256) void conv1_kernel(
    const float* __restrict__ x, const float* __restrict__ w,
    const float* __restrict__ bias)
{
    __shared__ float xs[20][20];
    __shared__ u64 ws2[25*32];     // [k][pair]
    __shared__ float bs[64];
    int b   = blockIdx.z;
    int ty0 = blockIdx.y * 16, tx0 = blockIdx.x * 16;
    int tid = threadIdx.y * 16 + threadIdx.x;

    for (int i = tid; i < 25*32; i += 256) {
        int k = i >> 5, p = i & 31;
        ws2[i] = packpair(w[(2*p)*25 + k], w[(2*p+1)*25 + k]);
    }
    if (tid < 64) bs[tid] = bias[tid];

    const float* xb = x + (size_t)b * HW1 * HW1;
    for (int i = tid; i < 400; i += 256) {
        int r = i / 20, c = i % 20;
        int gy = ty0 + r - 2, gx = tx0 + c - 2;
        float v = 0.f;
        if (gy >= 0 && gy < HW1 && gx >= 0 && gx < HW1) v = xb[gy*HW1 + gx];
        xs[r][c] = v;
    }
    __syncthreads();

    int ty = threadIdx.y, tx = threadIdx.x;
    u64 in2[25];
#pragma unroll
    for (int kh = 0; kh < 5; kh++)
#pragma unroll
        for (int kw = 0; kw < 5; kw++)
            in2[kh*5+kw] = pack2(xs[ty+kh][tx+kw]);

    int y = ty0 + ty, xc = tx0 + tx;
    float* hout = g_h + ((size_t)b*64)*HW1*HW1 + y*HW1 + xc;
#pragma unroll 4
    for (int p = 0; p < 32; p++) {
        u64 acc = packpair(bs[2*p], bs[2*p+1]);
#pragma unroll
        for (int k = 0; k < 25; k++) ffma2(acc, in2[k], ws2[k*32 + p]);
        float2 f = unpack2(acc);
        hout[(size_t)(2*p)*HW1*HW1]   = fmaxf(f.x, 0.f);
        hout[(size_t)(2*p+1)*HW1*HW1] = fmaxf(f.y, 0.f);
    }
}

// ============================================================
// conv2: k9 s2 + bias + capsule squash -> g_u[n][b][8]
// cp.async double-buffered staging; 4-row micro-tile.
// grid (7, 64) x 224 threads. (fp32 FFMA2 roofline ~500us)
// ============================================================
#define C2_WSZ 5184          // 81*64
#define C2_ISZ 960           // 15*64
#define C2_SMEM ((2*C2_WSZ + 2*C2_ISZ)*4)

__global__ __launch_bounds__(224) void conv2_kernel(const float* __restrict__ bias)
{
    extern __shared__ float dsm[];
    float* wsd = dsm;                 // [2][5184]
    float* ins = dsm + 2*C2_WSZ;      // [2][960]

    int b   = blockIdx.y;
    int t   = blockIdx.x;              // 0..6 -> output rows 4t..4t+3
    int tid = threadIdx.x;
    int ocg = tid & 7;
    int ow  = tid >> 3;
    int ow2 = ow * 2;

    u32 s_wsd = (u32)__cvta_generic_to_shared(wsd);
    u32 s_ins = (u32)__cvta_generic_to_shared(ins);

    const float* hb = g_h + (size_t)b*64*HW1*HW1 + (size_t)(8*t)*HW1;

    auto stage = [&](int ic, int buf) {
        u32 sw = s_wsd + buf*(C2_WSZ*4);
        u32 si = s_ins + buf*(C2_ISZ*4);
        const float* wsrc = g_wT + (size_t)ic*C2_WSZ;
        const float* isrc = hb + (size_t)ic*HW1*HW1;
#pragma unroll
        for (int k = 0; k < 6; k++) {
            int i = tid + k*224;
            if (i < 1296) cpasync16(sw + i*16, wsrc + i*4);
        }
#pragma unroll
        for (int k = 0; k < 2; k++) {
            int i = tid + k*224;
            if (i < 240) cpasync16(si + i*16, isrc + i*4);
        }
    };

    u64 acc[4][4];
#pragma unroll
    for (int r = 0; r < 4; r++)
#pragma unroll
        for (int k = 0; k < 4; k++) acc[r][k] = 0ull;

    stage(0, 0); cpcommit();

    for (int ic = 0; ic < 64; ic++) {
        int buf = ic & 1;
        cpwait0();
        __syncthreads();
        if (ic + 1 < 64) { stage(ic+1, buf ^ 1); cpcommit(); }

        const float* wb_ = wsd + buf*C2_WSZ;
        const float* ib_ = ins + buf*C2_ISZ;
#pragma unroll
        for (int kh = 0; kh < 9; kh++) {
#pragma unroll
            for (int kw = 0; kw < 9; kw++) {
                int q = kh*9 + kw;
                const u64* WA = (const u64*)&wb_[q*64 + ocg*4];
                const u64* WB = (const u64*)&wb_[q*64 + 32 + ocg*4];
                u64 wa0 = WA[0], wa1 = WA[1];
                u64 wb0 = WB[0], wb1 = WB[1];
#pragma unroll
                for (int r = 0; r < 4; r++) {
                    u64 iv = pack2(ib_[(kh + 2*r)*64 + ow2 + kw]);
                    ffma2(acc[r][0], iv, wa0); ffma2(acc[r][1], iv, wa1);
                    ffma2(acc[r][2], iv, wb0); ffma2(acc[r][3], iv, wb1);
                }
            }
        }
    }

    float bvals[8];
#pragma unroll
    for (int c = 0; c < 8; c++) bvals[c] = bias[ocg*8 + c];

#pragma unroll
    for (int r = 0; r < 4; r++) {
        float a[8];
#pragma unroll
        for (int k = 0; k < 4; k++) {
            float2 f = unpack2(acc[r][k]);
            a[2*k]   = f.x + bvals[2*k];
            a[2*k+1] = f.y + bvals[2*k+1];
        }
        float msq = 0.f;
#pragma unroll
        for (int c = 0; c < 8; c++) msq = fmaf(a[c], a[c], msq);
        float mag   = sqrtf(msq + EPS);
        float scale = msq / (1.f + msq) / (mag + EPS);
        int n = ocg*(HW2*HW2) + (4*t + r)*HW2 + ow;
        float* up = g_u + ((size_t)n*BATCH + b)*JDIM;   // [n][b][8]
        *(float4*)up       = make_float4(a[0]*scale, a[1]*scale, a[2]*scale, a[3]*scale);
        *(float4*)(up + 4) = make_float4(a[4]*scale, a[5]*scale, a[6]*scale, a[7]*scale);
    }
}

// ============================================================
// routing sweep: 320 threads (warp = o, lane = bb), grid (392,2)
// NPER=16, all W+u staged once via cp.async; u in split float4
// arrays (lane-contiguous -> conflict-free). smem 98.5KB,
// launch_bounds(320,2) -> 2 blocks/SM.
// iter0 sync-free; iter>=1 one sync per n (parity dbl-buf ex).
// ============================================================
#define R_WS   (NPER*1280)         // 20480 floats
#define R_USA  (NPER*32*4)         // 2048 floats
#define R_USB  (NPER*32*4)         // 2048 floats
#define R_EX   (2*NCAPS*32)        // 640 floats
#define R_SMEM ((R_WS + R_USA + R_USB + R_EX)*4)

__global__ __launch_bounds__(320, 2) void route_kernel(
    const float* __restrict__ W, int iter)
{
    extern __shared__ float dsm[];
    float* Ws  = dsm;                          // [16][1280]
    float* usA = dsm + R_WS;                   // [16][32] float4
    float* usB = dsm + R_WS + R_USA;           // [16][32] float4
    float* ex  = dsm + R_WS + R_USA + R_USB;   // [2][10][32]

    int tid  = threadIdx.x;          // 0..319
    int o    = tid >> 5;             // warp = capsule o
    int lane = tid & 31;
    int h    = blockIdx.y;           // bb half
    int bb   = h*32 + lane;
    int n0   = blockIdx.x * NPER;

    u32 s_ws  = (u32)__cvta_generic_to_shared(Ws);
    u32 s_usA = (u32)__cvta_generic_to_shared(usA);
    u32 s_usB = (u32)__cvta_generic_to_shared(usB);

    // stage all W: 5120 chunks = exactly 16 * 320
    const float* wsrc = W + (size_t)n0*1280;
#pragma unroll
    for (int k = 0; k < 16; k++) {
        int i = tid + k*320;
        cpasync16(s_ws + i*16, wsrc + (size_t)i*4);
    }
    // stage all u for this bb-half: 1024 chunks into split A/B arrays
#pragma unroll
    for (int k = 0; k < 4; k++) {
        int i = tid + k*320;
        if (i < 1024) {
            int nn   = i >> 6;
            int rem  = i & 63;
            int half = rem >> 5;
            int ll   = rem & 31;
            u32 dst  = (half ? s_usB : s_usA) + (nn*32 + ll)*16;
            const float* usrc = g_u + ((size_t)(n0+nn)*BATCH + h*32 + ll)*JDIM + half*4;
            cpasync16(dst, usrc);
        }
    }
    cpcommit();

    float v[16];
    if (iter > 0) {
        const float4* vp = (const float4*)(g_v + (bb*NCAPS + o)*ODIM);
#pragma unroll
        for (int k = 0; k < 4; k++) {
            float4 f = vp[k];
            v[4*k] = f.x; v[4*k+1] = f.y; v[4*k+2] = f.z; v[4*k+3] = f.w;
        }
    }

    float acc[16];
#pragma unroll
    for (int i = 0; i < 16; i++) acc[i] = 0.f;

    cpwait0();
    __syncthreads();

    for (int nn = 0; nn < NPER; nn++) {
        float4 ua = ((const float4*)usA)[nn*32 + lane];
        float4 ub = ((const float4*)usB)[nn*32 + lane];

        float uh[16];
        const float* wrow = Ws + nn*1280 + o*128;   // warp-uniform -> broadcast
#pragma unroll
        for (int i = 0; i < 16; i++) {
            float4 wa = *(const float4*)(wrow + i*8);
            float4 wb = *(const float4*)(wrow + i*8 + 4);
            float s = wa.x * ua.x;
            s = fmaf(wa.y, ua.y, s); s = fmaf(wa.z, ua.z, s); s = fmaf(wa.w, ua.w, s);
            s = fmaf(wb.x, ub.x, s); s = fmaf(wb.y, ub.y, s);
            s = fmaf(wb.z, ub.z, s); s = fmaf(wb.w, ub.w, s);
            uh[i] = s;
        }

        float c;
        if (iter == 0) {
            c = 0.1f;
        } else {
            float bnew = 0.f;
#pragma unroll
            for (int i = 0; i < 16; i++) bnew = fmaf(uh[i], v[i], bnew);
            float e = __expf(bnew);
            int par = nn & 1;
            ex[(par*NCAPS + o)*32 + lane] = e;
            __syncthreads();            // parity dbl-buf protects reuse
            float denom = 0.f;
#pragma unroll
            for (int k = 0; k < 10; k++) denom += ex[(par*NCAPS + k)*32 + lane];
            c = __fdividef(e, denom);
        }
#pragma unroll
        for (int i = 0; i < 16; i++) acc[i] = fmaf(c, uh[i], acc[i]);
    }

    int rep = (blockIdx.x*2 + blockIdx.y) & (NREP-1);
    float* sp = g_sR + rep*(BATCH*NCAPS*ODIM) + (bb*NCAPS + o)*ODIM;
#pragma unroll
    for (int i = 0; i < 16; i++) atomicAdd(&sp[i], acc[i]);
}

// ============================================================
// sum 8 replicas, squash -> v / out; re-zero replicas.
// mode 0: g_v = v0 ; mode 1: g_v += v1 ; mode 2: write out
// ============================================================
__global__ __launch_bounds__(256) void squash_v_kernel(float* __restrict__ out, int mode)
{
    int tid  = blockIdx.x*256 + threadIdx.x;
    int boq  = tid >> 2;
    int quad = tid & 3;

    float4 s = make_float4(0.f, 0.f, 0.f, 0.f);
#pragma unroll
    for (int r = 0; r < NREP; r++) {
        float* p = g_sR + r*(BATCH*NCAPS*ODIM) + boq*ODIM + quad*4;
        float4 t = *(const float4*)p;
        *(float4*)p = make_float4(0.f, 0.f, 0.f, 0.f);
        s.x += t.x; s.y += t.y; s.z += t.z; s.w += t.w;
    }

    float part = s.x*s.x + s.y*s.y + s.z*s.z + s.w*s.w;
    part += __shfl_xor_sync(0xffffffff, part, 1);
    part += __shfl_xor_sync(0xffffffff, part, 2);
    float msq   = part;
    float mag   = sqrtf(msq + EPS);
    float scale = msq / (1.f + msq) / (mag + EPS);
    float4 vv = make_float4(s.x*scale, s.y*scale, s.z*scale, s.w*scale);

    if (mode == 0) {
        *(float4*)(g_v + boq*ODIM + quad*4) = vv;
    } else if (mode == 1) {
        float4 old = *(const float4*)(g_v + boq*ODIM + quad*4);
        old.x += vv.x; old.y += vv.y; old.z += vv.z; old.w += vv.w;
        *(float4*)(g_v + boq*ODIM + quad*4) = old;
    } else {
        *(float4*)(out + boq*ODIM + quad*4) = vv;
    }
}

// ============================================================
extern "C" void kernel_launch(void* const* d_in, const int* in_sizes, int n_in,
                              void* d_out, int out_size)
{
    const float* x   = (const float*)d_in[0];
    const float* c1w = (const float*)d_in[1];
    const float* c1b = (const float*)d_in[2];
    const float* pw  = (const float*)d_in[3];
    const float* pb  = (const float*)d_in[4];
    const float* W   = (const float*)d_in[5];
    float* out = (float*)d_out;

    static int attr_done = 0;
    if (!attr_done) {
        cudaFuncSetAttribute(conv2_kernel, cudaFuncAttributeMaxDynamicSharedMemorySize, C2_SMEM);
        cudaFuncSetAttribute(route_kernel, cudaFuncAttributeMaxDynamicSharedMemorySize, R_SMEM);
        attr_done = 1;
    }

    w_transform_kernel<<<(64*64*81 + 255)/256, 256>>>(pw);
    conv1_kernel<<<dim3(4,4,64), dim3(16,16)>>>(x, c1w, c1b);
    conv2_kernel<<<dim3(7,64), 224, C2_SMEM>>>(pb);

    route_kernel<<<dim3(RBLOCKS,2), 320, R_SMEM>>>(W, 0);
    squash_v_kernel<<<10, 256>>>(out, 0);
    route_kernel<<<dim3(RBLOCKS,2), 320, R_SMEM>>>(W, 1);
    squash_v_kernel<<<10, 256>>>(out, 1);
    route_kernel<<<dim3(RBLOCKS,2), 320, R_SMEM>>>(W, 2);
    squash_v_kernel<<<10, 256>>>(out, 2);
}

// round 11
// speedup vs baseline: 1.1246x; 1.0014x over previous
#include <cuda_runtime.h>
#include <cstdint>
#include <math.h>

#define EPS 1e-9f

#define BATCH   64
#define HW1     64
#define HW2     28
#define NROUTES 6272
#define NCAPS   10
#define ODIM    16
#define JDIM    8

#define RBLOCKS 392
#define NPER    16       // n's per route block
#define NREP    8        // s-accumulator replicas

typedef unsigned long long u64;
typedef unsigned int       u32;

__device__ float g_h[(size_t)BATCH*64*HW1*HW1];      // conv1 out [b][ic][ih][iw]
__device__ float g_wT[64*81*64];                     // conv2 weights [ic][q][slot]
__device__ float g_u[(size_t)NROUTES*BATCH*JDIM];    // primary caps [n][b][8]
__device__ float g_v[BATCH*NCAPS*ODIM];              // v0, then v0+v1
__device__ float g_sR[NREP*BATCH*NCAPS*ODIM];        // replicated s accumulators

// ---------- packed fp32x2 helpers ----------
__device__ __forceinline__ u64 pack2(float x) {
    u64 r; asm("mov.b64 %0, {%1, %1};" : "=l"(r) : "f"(x)); return r;
}
__device__ __forceinline__ u64 packpair(float lo, float hi) {
    u64 r; asm("mov.b64 %0, {%1, %2};" : "=l"(r) : "f"(lo), "f"(hi)); return r;
}
__device__ __forceinline__ void ffma2(u64& d, u64 a, u64 b) {
    asm("fma.rn.f32x2 %0, %1, %2, %0;" : "+l"(d) : "l"(a), "l"(b));
}
__device__ __forceinline__ float2 unpack2(u64 a) {
    float2 f; asm("mov.b64 {%0, %1}, %2;" : "=f"(f.x), "=f"(f.y) : "l"(a)); return f;
}
// ---------- cp.async helpers ----------
__device__ __forceinline__ void cpasync16(u32 saddr, const void* gaddr) {
    asm volatile("cp.async.cg.shared.global [%0], [%1], 16;" :: "r"(saddr), "l"(gaddr));
}
__device__ __forceinline__ void cpcommit() {
    asm volatile("cp.async.commit_group;");
}
__device__ __forceinline__ void cpwait0() {
    asm volatile("cp.async.wait_group 0;");
}

// ============================================================
// one-time weight transpose for conv2:
// g_wT[ic][q][slot], slot = grp*4 + (c7&3) + (c7>=4 ? 32 : 0)
// ============================================================
__global__ __launch_bounds__(256) void w_transform_kernel(const float* __restrict__ w)
{
    int idx = blockIdx.x*256 + threadIdx.x;            // = oc*5184 + ic*81 + q
    if (idx >= 64*64*81) return;
    int oc  = idx / 5184;
    int rem = idx - oc*5184;
    int ic  = rem / 81;
    int q   = rem - ic*81;
    int c7  = oc & 7, grp = oc >> 3;
    int slot = grp*4 + (c7 & 3) + ((c7 >= 4) ? 32 : 0);
    g_wT[(size_t)ic*5184 + q*64 + slot] = w[idx];
}

// ============================================================
// conv1: (64,1,64,64) -> (64,64,64,64), k5 pad2 + bias + relu
// f32x2 over oc-pairs: 32 pairs x 25 taps FFMA2 per thread
// ============================================================
__global__ __launch_bounds__(256) void conv1_kernel(
    const float* __restrict__ x, const float* __restrict__ w,
    const float* __restrict__ bias)
{
    __shared__ float xs[20][20];
    __shared__ u64 ws2[25*32];     // [k][pair]
    __shared__ float bs[64];
    int b   = blockIdx.z;
    int ty0 = blockIdx.y * 16, tx0 = blockIdx.x * 16;
    int tid = threadIdx.y * 16 + threadIdx.x;

    for (int i = tid; i < 25*32; i += 256) {
        int k = i >> 5, p = i & 31;
        ws2[i] = packpair(w[(2*p)*25 + k], w[(2*p+1)*25 + k]);
    }
    if (tid < 64) bs[tid] = bias[tid];

    const float* xb = x + (size_t)b * HW1 * HW1;
    for (int i = tid; i < 400; i += 256) {
        int r = i / 20, c = i % 20;
        int gy = ty0 + r - 2, gx = tx0 + c - 2;
        float v = 0.f;
        if (gy >= 0 && gy < HW1 && gx >= 0 && gx < HW1) v = xb[gy*HW1 + gx];
        xs[r][c] = v;
    }
    __syncthreads();

    int ty = threadIdx.y, tx = threadIdx.x;
    u64 in2[25];
#pragma unroll
    for (int kh = 0; kh < 5; kh++)
#pragma unroll
        for (int kw = 0; kw < 5; kw++)
            in2[kh*5+kw] = pack2(xs[ty+kh][tx+kw]);

    int y = ty0 + ty, xc = tx0 + tx;
    float* hout = g_h + ((size_t)b*64)*HW1*HW1 + y*HW1 + xc;
#pragma unroll 4
    for (int p = 0; p < 32; p++) {
        u64 acc = packpair(bs[2*p], bs[2*p+1]);
#pragma unroll
        for (int k = 0; k < 25; k++) ffma2(acc, in2[k], ws2[k*32 + p]);
        float2 f = unpack2(acc);
        hout[(size_t)(2*p)*HW1*HW1]   = fmaxf(f.x, 0.f);
        hout[(size_t)(2*p+1)*HW1*HW1] = fmaxf(f.y, 0.f);
    }
}

// ============================================================
// conv2: k9 s2 + bias + capsule squash -> g_u[n][b][8]
// cp.async double-buffered staging; 4-row micro-tile.
// grid (7, 64) x 224 threads. (fp32 FFMA2 roofline ~500us)
// ============================================================
#define C2_WSZ 5184          // 81*64
#define C2_ISZ 960           // 15*64
#define C2_SMEM ((2*C2_WSZ + 2*C2_ISZ)*4)

__global__ __launch_bounds__(224) void conv2_kernel(const float* __restrict__ bias)
{
    extern __shared__ float dsm[];
    float* wsd = dsm;                 // [2][5184]
    float* ins = dsm + 2*C2_WSZ;      // [2][960]

    int b   = blockIdx.y;
    int t   = blockIdx.x;              // 0..6 -> output rows 4t..4t+3
    int tid = threadIdx.x;
    int ocg = tid & 7;
    int ow  = tid >> 3;
    int ow2 = ow * 2;

    u32 s_wsd = (u32)__cvta_generic_to_shared(wsd);
    u32 s_ins = (u32)__cvta_generic_to_shared(ins);

    const float* hb = g_h + (size_t)b*64*HW1*HW1 + (size_t)(8*t)*HW1;

    auto stage = [&](int ic, int buf) {
        u32 sw = s_wsd + buf*(C2_WSZ*4);
        u32 si = s_ins + buf*(C2_ISZ*4);
        const float* wsrc = g_wT + (size_t)ic*C2_WSZ;
        const float* isrc = hb + (size_t)ic*HW1*HW1;
#pragma unroll
        for (int k = 0; k < 6; k++) {
            int i = tid + k*224;
            if (i < 1296) cpasync16(sw + i*16, wsrc + i*4);
        }
#pragma unroll
        for (int k = 0; k < 2; k++) {
            int i = tid + k*224;
            if (i < 240) cpasync16(si + i*16, isrc + i*4);
        }
    };

    u64 acc[4][4];
#pragma unroll
    for (int r = 0; r < 4; r++)
#pragma unroll
        for (int k = 0; k < 4; k++) acc[r][k] = 0ull;

    stage(0, 0); cpcommit();

    for (int ic = 0; ic < 64; ic++) {
        int buf = ic & 1;
        cpwait0();
        __syncthreads();
        if (ic + 1 < 64) { stage(ic+1, buf ^ 1); cpcommit(); }

        const float* wb_ = wsd + buf*C2_WSZ;
        const float* ib_ = ins + buf*C2_ISZ;
#pragma unroll
        for (int kh = 0; kh < 9; kh++) {
#pragma unroll
            for (int kw = 0; kw < 9; kw++) {
                int q = kh*9 + kw;
                const u64* WA = (const u64*)&wb_[q*64 + ocg*4];
                const u64* WB = (const u64*)&wb_[q*64 + 32 + ocg*4];
                u64 wa0 = WA[0], wa1 = WA[1];
                u64 wb0 = WB[0], wb1 = WB[1];
#pragma unroll
                for (int r = 0; r < 4; r++) {
                    u64 iv = pack2(ib_[(kh + 2*r)*64 + ow2 + kw]);
                    ffma2(acc[r][0], iv, wa0); ffma2(acc[r][1], iv, wa1);
                    ffma2(acc[r][2], iv, wb0); ffma2(acc[r][3], iv, wb1);
                }
            }
        }
    }

    float bvals[8];
#pragma unroll
    for (int c = 0; c < 8; c++) bvals[c] = bias[ocg*8 + c];

#pragma unroll
    for (int r = 0; r < 4; r++) {
        float a[8];
#pragma unroll
        for (int k = 0; k < 4; k++) {
            float2 f = unpack2(acc[r][k]);
            a[2*k]   = f.x + bvals[2*k];
            a[2*k+1] = f.y + bvals[2*k+1];
        }
        float msq = 0.f;
#pragma unroll
        for (int c = 0; c < 8; c++) msq = fmaf(a[c], a[c], msq);
        float mag   = sqrtf(msq + EPS);
        float scale = msq / (1.f + msq) / (mag + EPS);
        int n = ocg*(HW2*HW2) + (4*t + r)*HW2 + ow;
        float* up = g_u + ((size_t)n*BATCH + b)*JDIM;   // [n][b][8]
        *(float4*)up       = make_float4(a[0]*scale, a[1]*scale, a[2]*scale, a[3]*scale);
        *(float4*)(up + 4) = make_float4(a[4]*scale, a[5]*scale, a[6]*scale, a[7]*scale);
    }
}

// ============================================================
// routing sweep: 320 threads (warp = o, lane = bb), grid (392,2)
// NPER=16, all W+u staged once via cp.async; u in split float4
// arrays (lane-contiguous -> conflict-free). smem 98.5KB,
// launch_bounds(320,2) -> 2 blocks/SM.
// iter0 sync-free; iter>=1 one sync per n (parity dbl-buf ex).
// ============================================================
#define R_WS   (NPER*1280)         // 20480 floats
#define R_USA  (NPER*32*4)         // 2048 floats
#define R_USB  (NPER*32*4)         // 2048 floats
#define R_EX   (2*NCAPS*32)        // 640 floats
#define R_SMEM ((R_WS + R_USA + R_USB + R_EX)*4)

__global__ __launch_bounds__(320, 2) void route_kernel(
    const float* __restrict__ W, int iter)
{
    extern __shared__ float dsm[];
    float* Ws  = dsm;                          // [16][1280]
    float* usA = dsm + R_WS;                   // [16][32] float4
    float* usB = dsm + R_WS + R_USA;           // [16][32] float4
    float* ex  = dsm + R_WS + R_USA + R_USB;   // [2][10][32]

    int tid  = threadIdx.x;          // 0..319
    int o    = tid >> 5;             // warp = capsule o
    int lane = tid & 31;
    int h    = blockIdx.y;           // bb half
    int bb   = h*32 + lane;
    int n0   = blockIdx.x * NPER;

    u32 s_ws  = (u32)__cvta_generic_to_shared(Ws);
    u32 s_usA = (u32)__cvta_generic_to_shared(usA);
    u32 s_usB = (u32)__cvta_generic_to_shared(usB);

    // stage all W: 5120 chunks = exactly 16 * 320
    const float* wsrc = W + (size_t)n0*1280;
#pragma unroll
    for (int k = 0; k < 16; k++) {
        int i = tid + k*320;
        cpasync16(s_ws + i*16, wsrc + (size_t)i*4);
    }
    // stage all u for this bb-half: 1024 chunks into split A/B arrays
#pragma unroll
    for (int k = 0; k < 4; k++) {
        int i = tid + k*320;
        if (i < 1024) {
            int nn   = i >> 6;
            int rem  = i & 63;
            int half = rem >> 5;
            int ll   = rem & 31;
            u32 dst  = (half ? s_usB : s_usA) + (nn*32 + ll)*16;
            const float* usrc = g_u + ((size_t)(n0+nn)*BATCH + h*32 + ll)*JDIM + half*4;
            cpasync16(dst, usrc);
        }
    }
    cpcommit();

    float v[16];
    if (iter > 0) {
        const float4* vp = (const float4*)(g_v + (bb*NCAPS + o)*ODIM);
#pragma unroll
        for (int k = 0; k < 4; k++) {
            float4 f = vp[k];
            v[4*k] = f.x; v[4*k+1] = f.y; v[4*k+2] = f.z; v[4*k+3] = f.w;
        }
    }

    float acc[16];
#pragma unroll
    for (int i = 0; i < 16; i++) acc[i] = 0.f;

    cpwait0();
    __syncthreads();

    for (int nn = 0; nn < NPER; nn++) {
        float4 ua = ((const float4*)usA)[nn*32 + lane];
        float4 ub = ((const float4*)usB)[nn*32 + lane];

        float uh[16];
        const float* wrow = Ws + nn*1280 + o*128;   // warp-uniform -> broadcast
#pragma unroll
        for (int i = 0; i < 16; i++) {
            float4 wa = *(const float4*)(wrow + i*8);
            float4 wb = *(const float4*)(wrow + i*8 + 4);
            float s = wa.x * ua.x;
            s = fmaf(wa.y, ua.y, s); s = fmaf(wa.z, ua.z, s); s = fmaf(wa.w, ua.w, s);
            s = fmaf(wb.x, ub.x, s); s = fmaf(wb.y, ub.y, s);
            s = fmaf(wb.z, ub.z, s); s = fmaf(wb.w, ub.w, s);
            uh[i] = s;
        }

        float c;
        if (iter == 0) {
            c = 0.1f;
        } else {
            float bnew = 0.f;
#pragma unroll
            for (int i = 0; i < 16; i++) bnew = fmaf(uh[i], v[i], bnew);
            float e = __expf(bnew);
            int par = nn & 1;
            ex[(par*NCAPS + o)*32 + lane] = e;
            __syncthreads();            // parity dbl-buf protects reuse
            float denom = 0.f;
#pragma unroll
            for (int k = 0; k < 10; k++) denom += ex[(par*NCAPS + k)*32 + lane];
            c = __fdividef(e, denom);
        }
#pragma unroll
        for (int i = 0; i < 16; i++) acc[i] = fmaf(c, uh[i], acc[i]);
    }

    int rep = (blockIdx.x*2 + blockIdx.y) & (NREP-1);
    float* sp = g_sR + rep*(BATCH*NCAPS*ODIM) + (bb*NCAPS + o)*ODIM;
#pragma unroll
    for (int i = 0; i < 16; i++) atomicAdd(&sp[i], acc[i]);
}

// ============================================================
// sum 8 replicas, squash -> v / out; re-zero replicas.
// mode 0: g_v = v0 ; mode 1: g_v += v1 ; mode 2: write out
// ============================================================
__global__ __launch_bounds__(256) void squash_v_kernel(float* __restrict__ out, int mode)
{
    int tid  = blockIdx.x*256 + threadIdx.x;
    int boq  = tid >> 2;
    int quad = tid & 3;

    float4 s = make_float4(0.f, 0.f, 0.f, 0.f);
#pragma unroll
    for (int r = 0; r < NREP; r++) {
        float* p = g_sR + r*(BATCH*NCAPS*ODIM) + boq*ODIM + quad*4;
        float4 t = *(const float4*)p;
        *(float4*)p = make_float4(0.f, 0.f, 0.f, 0.f);
        s.x += t.x; s.y += t.y; s.z += t.z; s.w += t.w;
    }

    float part = s.x*s.x + s.y*s.y + s.z*s.z + s.w*s.w;
    part += __shfl_xor_sync(0xffffffff, part, 1);
    part += __shfl_xor_sync(0xffffffff, part, 2);
    float msq   = part;
    float mag   = sqrtf(msq + EPS);
    float scale = msq / (1.f + msq) / (mag + EPS);
    float4 vv = make_float4(s.x*scale, s.y*scale, s.z*scale, s.w*scale);

    if (mode == 0) {
        *(float4*)(g_v + boq*ODIM + quad*4) = vv;
    } else if (mode == 1) {
        float4 old = *(const float4*)(g_v + boq*ODIM + quad*4);
        old.x += vv.x; old.y += vv.y; old.z += vv.z; old.w += vv.w;
        *(float4*)(g_v + boq*ODIM + quad*4) = old;
    } else {
        *(float4*)(out + boq*ODIM + quad*4) = vv;
    }
}

// ============================================================
extern "C" void kernel_launch(void* const* d_in, const int* in_sizes, int n_in,
                              void* d_out, int out_size)
{
    const float* x   = (const float*)d_in[0];
    const float* c1w = (const float*)d_in[1];
    const float* c1b = (const float*)d_in[2];
    const float* pw  = (const float*)d_in[3];
    const float* pb  = (const float*)d_in[4];
    const float* W   = (const float*)d_in[5];
    float* out = (float*)d_out;

    static int attr_done = 0;
    if (!attr_done) {
        cudaFuncSetAttribute(conv2_kernel, cudaFuncAttributeMaxDynamicSharedMemorySize, C2_SMEM);
        cudaFuncSetAttribute(route_kernel, cudaFuncAttributeMaxDynamicSharedMemorySize, R_SMEM);
        attr_done = 1;
    }

    w_transform_kernel<<<(64*64*81 + 255)/256, 256>>>(pw);
    conv1_kernel<<<dim3(4,4,64), dim3(16,16)>>>(x, c1w, c1b);
    conv2_kernel<<<dim3(7,64), 224, C2_SMEM>>>(pb);

    route_kernel<<<dim3(RBLOCKS,2), 320, R_SMEM>>>(W, 0);
    squash_v_kernel<<<10, 256>>>(out, 0);
    route_kernel<<<dim3(RBLOCKS,2), 320, R_SMEM>>>(W, 1);
    squash_v_kernel<<<10, 256>>>(out, 1);
    route_kernel<<<dim3(RBLOCKS,2), 320, R_SMEM>>>(W, 2);
    squash_v_kernel<<<10, 256>>>(out, 2);
}

// round 14
// speedup vs baseline: 1.1576x; 1.0293x over previous
#include <cuda_runtime.h>
#include <cuda_bf16.h>
#include <cstdint>
#include <math.h>

#define EPS 1e-9f
#define BATCH 64
#define HW1 64
#define HW2 28
#define NROUTES 6272
#define NCAPS 10
#define ODIM 16
#define JDIM 8
#define RBLOCKS 392
#define NPER 16
#define NREP 8

typedef unsigned long long u64;
typedef unsigned int u32;

__device__ float g_h[(size_t)BATCH*64*HW1*HW1];
__device__ __nv_bfloat16 g_wbf2[64*2*64*96];         // [ic][split][oc][96]
__device__ float g_u[(size_t)NROUTES*BATCH*JDIM];    // [n][b][8]
__device__ float g_v[BATCH*NCAPS*ODIM];
__device__ float g_sR[NREP*BATCH*NCAPS*ODIM];

__device__ __forceinline__ u64 pack2(float x){u64 r;asm("mov.b64 %0,{%1,%1};":"=l"(r):"f"(x));return r;}
__device__ __forceinline__ u64 packpair(float a,float b){u64 r;asm("mov.b64 %0,{%1,%2};":"=l"(r):"f"(a),"f"(b));return r;}
__device__ __forceinline__ void ffma2(u64&d,u64 a,u64 b){asm("fma.rn.f32x2 %0,%1,%2,%0;":"+l"(d):"l"(a),"l"(b));}
__device__ __forceinline__ float2 unpack2(u64 a){float2 f;asm("mov.b64 {%0,%1},%2;":"=f"(f.x),"=f"(f.y):"l"(a));return f;}
__device__ __forceinline__ void cpasync16(u32 s,const void* g){asm volatile("cp.async.cg.shared.global [%0],[%1],16;"::"r"(s),"l"(g));}
__device__ __forceinline__ void cpcommit(){asm volatile("cp.async.commit_group;");}
__device__ __forceinline__ void cpwait0(){asm volatile("cp.async.wait_group 0;");}

__device__ __forceinline__ void ldsm_x4(u32& r0,u32& r1,u32& r2,u32& r3,u32 a){
    asm volatile("ldmatrix.sync.aligned.m8n8.x4.shared.b16 {%0,%1,%2,%3},[%4];"
        :"=r"(r0),"=r"(r1),"=r"(r2),"=r"(r3):"r"(a));
}
__device__ __forceinline__ void mma_bf16(float* d,const u32* a,u32 b0,u32 b1){
    asm volatile("mma.sync.aligned.m16n8k16.row.col.f32.bf16.bf16.f32 "
        "{%0,%1,%2,%3},{%4,%5,%6,%7},{%8,%9},{%0,%1,%2,%3};"
        :"+f"(d[0]),"+f"(d[1]),"+f"(d[2]),"+f"(d[3])
        :"r"(a[0]),"r"(a[1]),"r"(a[2]),"r"(a[3]),"r"(b0),"r"(b1));
}

// ============================================================
// one-time: conv2 weights -> bf16 hi/lo [ic][split][oc][96]
__global__ __launch_bounds__(256) void wbf_transform_kernel(const float* __restrict__ w)
{
    int idx = blockIdx.x*256 + threadIdx.x;
    if (idx >= 64*2*64*96) return;
    int ic = idx / 12288;
    int rem = idx - ic*12288;
    int s = rem / 6144;
    int oc = (rem / 96) & 63;
    int k = rem % 96;
    float val = (k < 81) ? w[(size_t)(oc*64+ic)*81 + k] : 0.f;
    __nv_bfloat16 hi = __float2bfloat16(val);
    g_wbf2[idx] = s ? __float2bfloat16(val - __bfloat162float(hi)) : hi;
}

// ============================================================
// conv1 (unchanged, f32x2)
__global__ __launch_bounds__(256) void conv1_kernel(
    const float* __restrict__ x, const float* __restrict__ w, const float* __restrict__ bias)
{
    __shared__ float xs[20][20];
    __shared__ u64 ws2[25*32];
    __shared__ float bs[64];
    int b = blockIdx.z, ty0 = blockIdx.y*16, tx0 = blockIdx.x*16;
    int tid = threadIdx.y*16 + threadIdx.x;
    for (int i = tid; i < 25*32; i += 256) {
        int k = i>>5, p = i&31;
        ws2[i] = packpair(w[(2*p)*25+k], w[(2*p+1)*25+k]);
    }
    if (tid < 64) bs[tid] = bias[tid];
    const float* xb = x + (size_t)b*HW1*HW1;
    for (int i = tid; i < 400; i += 256) {
        int r = i/20, c = i%20, gy = ty0+r-2, gx = tx0+c-2;
        float v = 0.f;
        if (gy>=0 && gy<HW1 && gx>=0 && gx<HW1) v = xb[gy*HW1+gx];
        xs[r][c] = v;
    }
    __syncthreads();
    int ty = threadIdx.y, tx = threadIdx.x;
    u64 in2[25];
#pragma unroll
    for (int kh = 0; kh < 5; kh++)
#pragma unroll
        for (int kw = 0; kw < 5; kw++) in2[kh*5+kw] = pack2(xs[ty+kh][tx+kw]);
    float* hout = g_h + ((size_t)b*64)*HW1*HW1 + (ty0+ty)*HW1 + tx0+tx;
#pragma unroll 4
    for (int p = 0; p < 32; p++) {
        u64 acc = packpair(bs[2*p], bs[2*p+1]);
#pragma unroll
        for (int k = 0; k < 25; k++) ffma2(acc, in2[k], ws2[k*32+p]);
        float2 f = unpack2(acc);
        hout[(size_t)(2*p)*HW1*HW1]   = fmaxf(f.x, 0.f);
        hout[(size_t)(2*p+1)*HW1*HW1] = fmaxf(f.y, 0.f);
    }
}

// ============================================================
// conv2 via mma.sync bf16 split-3: block (b, t=4 rows)
// GEMM D[128 pix][64 oc] += A[pix][96k] B[oc][96k]^T per ic.
// B memory [n][k] = col-major k x n -> NON-trans ldmatrix on n-rows.
#define APITCH 208
#define A_HI 0
#define A_LO 26624
#define B_OFF 53248          // [buf][split][64][208B]
#define INS_OFF 106496       // [buf][960 floats]
#define TC_BYTES 114176
#define TC_SMEM (TC_BYTES + 1024)

__global__ __launch_bounds__(256, 1) void conv2_mma_kernel(const float* __restrict__ bias)
{
    extern __shared__ char smraw[];
    char* sm = (char*)((((size_t)smraw) + 1023) & ~(size_t)1023);
    u32 smb = (u32)__cvta_generic_to_shared(sm);

    int tid = threadIdx.x, w = tid>>5, lane = tid&31;
    int b = blockIdx.y, t = blockIdx.x;

    // zero A (pads: k 84..95, pixel rows 112..127 stay zero)
    for (int i = tid; i < 13312; i += 256) ((u32*)sm)[i] = 0;

    // im2col constants
    bool act = tid < 224;
    int p = act ? (tid % 112) : 0;
    int seg = act ? (tid / 112) : 0;
    int pr = p/28, ow = p - pr*28;
    int inbase = pr*128 + 2*ow;
    int j0 = seg*21;

    const float* insrc = g_h + (size_t)b*64*4096 + (size_t)(8*t)*64;

    auto stageB = [&](int ic, int buf) {
        const __nv_bfloat16* src = g_wbf2 + (size_t)ic*12288;
        u32 dstb = smb + B_OFF + buf*26624;
#pragma unroll
        for (int k = 0; k < 6; k++) {
            int i = tid + k*256;          // 0..1535
            int s = i / 768;
            int r = i - s*768;
            int n = r / 12, c = r - n*12;
            cpasync16(dstb + s*13312 + n*APITCH + c*16, src + (size_t)s*6144 + n*96 + c*8);
        }
    };
    auto stageI = [&](int ic, int buf) {
        if (tid < 240)
            cpasync16(smb + INS_OFF + buf*3840 + tid*16, insrc + (size_t)ic*4096 + tid*4);
    };

    float acc[8][4];
#pragma unroll
    for (int nt = 0; nt < 8; nt++)
#pragma unroll
        for (int k = 0; k < 4; k++) acc[nt][k] = 0.f;

    stageB(0, 0); stageI(0, 0); cpcommit();

    // ldmatrix lane addresses (fixed parts)
    u32 a_row  = (u32)(w*16 + (lane & 15));
    u32 a_kofs = (u32)((lane >> 4) * 8);
    u32 b_nrow = (u32)((lane & 7) + (lane >> 4)*8);
    u32 b_kofs = (u32)(((lane >> 3) & 1) * 8);

    for (int ic = 0; ic < 64; ic++) {
        int cur = ic & 1;
        cpwait0();
        __syncthreads();                 // staged(cur) ready; prev mma done

        // im2col A hi/lo for this ic
        if (act) {
            const float* insf = (const float*)(sm + INS_OFF + cur*3840);
#pragma unroll
            for (int jj = 0; jj < 21; jj++) {
                int j = j0 + jj;
                if (j > 41) break;
                int q0 = 2*j, q1 = q0+1;
                float v0 = 0.f, v1 = 0.f;
                if (q0 <= 80) {
                    int kh0 = (q0*456)>>12, kw0 = q0 - kh0*9;
                    v0 = insf[inbase + kh0*64 + kw0];
                }
                if (q1 <= 80) {
                    int kh1 = (q1*456)>>12, kw1 = q1 - kh1*9;
                    v1 = insf[inbase + kh1*64 + kw1];
                }
                __nv_bfloat16 h0 = __float2bfloat16(v0), h1 = __float2bfloat16(v1);
                __nv_bfloat16 l0 = __float2bfloat16(v0 - __bfloat162float(h0));
                __nv_bfloat16 l1 = __float2bfloat16(v1 - __bfloat162float(h1));
                u32 whi = (u32)__bfloat16_as_ushort(h0) | ((u32)__bfloat16_as_ushort(h1)<<16);
                u32 wlo = (u32)__bfloat16_as_ushort(l0) | ((u32)__bfloat16_as_ushort(l1)<<16);
                int off = p*APITCH + j*4;
                *(u32*)(sm + A_HI + off) = whi;
                *(u32*)(sm + A_LO + off) = wlo;
            }
        }
        if (ic < 63) { stageB(ic+1, cur^1); stageI(ic+1, cur^1); cpcommit(); }
        __syncthreads();                 // A ready

        u32 bbase = smb + B_OFF + cur*26624;
#pragma unroll
        for (int sp = 0; sp < 3; sp++) {
            u32 abase = smb + ((sp == 1) ? A_LO : A_HI);
            u32 bsp   = bbase + ((sp == 2) ? 13312 : 0);
#pragma unroll
            for (int ks = 0; ks < 6; ks++) {
                u32 k0 = ks*16;
                u32 a[4];
                ldsm_x4(a[0], a[1], a[2], a[3], abase + a_row*APITCH + (k0 + a_kofs)*2);
#pragma unroll
                for (int ntp = 0; ntp < 4; ntp++) {
                    u32 bf[4];
                    ldsm_x4(bf[0], bf[1], bf[2], bf[3],
                            bsp + (ntp*16 + b_nrow)*APITCH + (k0 + b_kofs)*2);
                    mma_bf16(acc[2*ntp],   a, bf[0], bf[1]);
                    mma_bf16(acc[2*ntp+1], a, bf[2], bf[3]);
                }
            }
        }
    }

    // epilogue: lane holds cols (lane%4)*2,+1 of each n-tile, rows w*16+l/4 and +8
    if (w < 7) {
        int c2 = (lane & 3)*2;
        float b0v[8], b1v[8];
#pragma unroll
        for (int nt = 0; nt < 8; nt++) { b0v[nt] = bias[nt*8 + c2]; b1v[nt] = bias[nt*8 + c2 + 1]; }
#pragma unroll
        for (int rr = 0; rr < 2; rr++) {
            int pp = w*16 + (lane >> 2) + rr*8;
            int n_base = 112*t + pp;
#pragma unroll
            for (int nt = 0; nt < 8; nt++) {
                float a0 = acc[nt][rr*2]   + b0v[nt];
                float a1 = acc[nt][rr*2+1] + b1v[nt];
                float part = a0*a0 + a1*a1;
                part += __shfl_xor_sync(0xffffffff, part, 1);
                part += __shfl_xor_sync(0xffffffff, part, 2);
                float mag = sqrtf(part + EPS);
                float scale = part/(1.f+part)/(mag+EPS);
                float* up = g_u + ((size_t)(nt*784 + n_base)*BATCH + b)*JDIM + c2;
                *(float2*)up = make_float2(a0*scale, a1*scale);
            }
        }
    }
}

// ============================================================
// routing sweep (unchanged from 915us build)
#define R_WS  (NPER*1280)
#define R_USA (NPER*32*4)
#define R_USB (NPER*32*4)
#define R_EX  (2*NCAPS*32)
#define R_SMEM ((R_WS + R_USA + R_USB + R_EX)*4)

__global__ __launch_bounds__(320, 2) void route_kernel(const float* __restrict__ W, int iter)
{
    extern __shared__ float dsm[];
    float* Ws  = dsm;
    float* usA = dsm + R_WS;
    float* usB = dsm + R_WS + R_USA;
    float* ex  = dsm + R_WS + R_USA + R_USB;

    int tid = threadIdx.x, o = tid>>5, lane = tid&31;
    int h = blockIdx.y, bb = h*32 + lane;
    int n0 = blockIdx.x * NPER;

    u32 s_ws  = (u32)__cvta_generic_to_shared(Ws);
    u32 s_usA = (u32)__cvta_generic_to_shared(usA);
    u32 s_usB = (u32)__cvta_generic_to_shared(usB);

    const float* wsrc = W + (size_t)n0*1280;
#pragma unroll
    for (int k = 0; k < 16; k++) {
        int i = tid + k*320;
        cpasync16(s_ws + i*16, wsrc + (size_t)i*4);
    }
#pragma unroll
    for (int k = 0; k < 4; k++) {
        int i = tid + k*320;
        if (i < 1024) {
            int nn = i>>6, rem = i&63, half = rem>>5, ll = rem&31;
            u32 dst = (half ? s_usB : s_usA) + (nn*32 + ll)*16;
            cpasync16(dst, g_u + ((size_t)(n0+nn)*BATCH + h*32 + ll)*JDIM + half*4);
        }
    }
    cpcommit();

    float v[16];
    if (iter > 0) {
        const float4* vp = (const float4*)(g_v + (bb*NCAPS + o)*ODIM);
#pragma unroll
        for (int k = 0; k < 4; k++) {
            float4 f = vp[k];
            v[4*k]=f.x; v[4*k+1]=f.y; v[4*k+2]=f.z; v[4*k+3]=f.w;
        }
    }
    float acc[16];
#pragma unroll
    for (int i = 0; i < 16; i++) acc[i] = 0.f;

    cpwait0();
    __syncthreads();

    for (int nn = 0; nn < NPER; nn++) {
        float4 ua = ((const float4*)usA)[nn*32 + lane];
        float4 ub = ((const float4*)usB)[nn*32 + lane];
        float uh[16];
        const float* wrow = Ws + nn*1280 + o*128;
#pragma unroll
        for (int i = 0; i < 16; i++) {
            float4 wa = *(const float4*)(wrow + i*8);
            float4 wb = *(const float4*)(wrow + i*8 + 4);
            float s = wa.x*ua.x;
            s = fmaf(wa.y,ua.y,s); s = fmaf(wa.z,ua.z,s); s = fmaf(wa.w,ua.w,s);
            s = fmaf(wb.x,ub.x,s); s = fmaf(wb.y,ub.y,s);
            s = fmaf(wb.z,ub.z,s); s = fmaf(wb.w,ub.w,s);
            uh[i] = s;
        }
        float c;
        if (iter == 0) c = 0.1f;
        else {
            float bnew = 0.f;
#pragma unroll
            for (int i = 0; i < 16; i++) bnew = fmaf(uh[i], v[i], bnew);
            float e = __expf(bnew);
            int par = nn & 1;
            ex[(par*NCAPS + o)*32 + lane] = e;
            __syncthreads();
            float denom = 0.f;
#pragma unroll
            for (int k = 0; k < 10; k++) denom += ex[(par*NCAPS + k)*32 + lane];
            c = __fdividef(e, denom);
        }
#pragma unroll
        for (int i = 0; i < 16; i++) acc[i] = fmaf(c, uh[i], acc[i]);
    }
    int rep = (blockIdx.x*2 + blockIdx.y) & (NREP-1);
    float* sp = g_sR + rep*(BATCH*NCAPS*ODIM) + (bb*NCAPS + o)*ODIM;
#pragma unroll
    for (int i = 0; i < 16; i++) atomicAdd(&sp[i], acc[i]);
}

// ============================================================
__global__ __launch_bounds__(256) void squash_v_kernel(float* __restrict__ out, int mode)
{
    int tid = blockIdx.x*256 + threadIdx.x;
    int boq = tid>>2, quad = tid&3;
    float4 s = make_float4(0.f,0.f,0.f,0.f);
#pragma unroll
    for (int r = 0; r < NREP; r++) {
        float* p = g_sR + r*(BATCH*NCAPS*ODIM) + boq*ODIM + quad*4;
        float4 t = *(const float4*)p;
        *(float4*)p = make_float4(0.f,0.f,0.f,0.f);
        s.x += t.x; s.y += t.y; s.z += t.z; s.w += t.w;
    }
    float part = s.x*s.x + s.y*s.y + s.z*s.z + s.w*s.w;
    part += __shfl_xor_sync(0xffffffff, part, 1);
    part += __shfl_xor_sync(0xffffffff, part, 2);
    float msq = part;
    float mag = sqrtf(msq + EPS);
    float scale = msq/(1.f+msq)/(mag+EPS);
    float4 vv = make_float4(s.x*scale, s.y*scale, s.z*scale, s.w*scale);
    if (mode == 0) *(float4*)(g_v + boq*ODIM + quad*4) = vv;
    else if (mode == 1) {
        float4 old = *(const float4*)(g_v + boq*ODIM + quad*4);
        old.x += vv.x; old.y += vv.y; old.z += vv.z; old.w += vv.w;
        *(float4*)(g_v + boq*ODIM + quad*4) = old;
    } else *(float4*)(out + boq*ODIM + quad*4) = vv;
}

// ============================================================
extern "C" void kernel_launch(void* const* d_in, const int* in_sizes, int n_in,
                              void* d_out, int out_size)
{
    const float* x   = (const float*)d_in[0];
    const float* c1w = (const float*)d_in[1];
    const float* c1b = (const float*)d_in[2];
    const float* pw  = (const float*)d_in[3];
    const float* pb  = (const float*)d_in[4];
    const float* W   = (const float*)d_in[5];
    float* out = (float*)d_out;

    static int attr_done = 0;
    if (!attr_done) {
        cudaFuncSetAttribute(conv2_mma_kernel, cudaFuncAttributeMaxDynamicSharedMemorySize, TC_SMEM);
        cudaFuncSetAttribute(route_kernel, cudaFuncAttributeMaxDynamicSharedMemorySize, R_SMEM);
        attr_done = 1;
    }

    wbf_transform_kernel<<<(64*2*64*96 + 255)/256, 256>>>(pw);
    conv1_kernel<<<dim3(4,4,64), dim3(16,16)>>>(x, c1w, c1b);
    conv2_mma_kernel<<<dim3(7,64), 256, TC_SMEM>>>(pb);

    route_kernel<<<dim3(RBLOCKS,2), 320, R_SMEM>>>(W, 0);
    squash_v_kernel<<<10, 256>>>(out, 0);
    route_kernel<<<dim3(RBLOCKS,2), 320, R_SMEM>>>(W, 1);
    squash_v_kernel<<<10, 256>>>(out, 1);
    route_kernel<<<dim3(RBLOCKS,2), 320, R_SMEM>>>(W, 2);
    squash_v_kernel<<<10, 256>>>(out, 2);
}

// round 15
// speedup vs baseline: 1.1577x; 1.0001x over previous
#include <cuda_runtime.h>
#include <cuda_bf16.h>
#include <cstdint>
#include <math.h>

#define EPS 1e-9f
#define BATCH 64
#define HW1 64
#define HW2 28
#define NROUTES 6272
#define NCAPS 10
#define ODIM 16
#define JDIM 8
#define RBLOCKS 392
#define NPER 16
#define NREP 8

typedef unsigned long long u64;
typedef unsigned int u32;

__device__ float g_h[(size_t)BATCH*64*HW1*HW1];
__device__ __nv_bfloat16 g_wbf2[64*2*64*96];         // [ic][split][oc][96]
__device__ float g_u[(size_t)NROUTES*BATCH*JDIM];    // [n][b][8]
__device__ float g_v[BATCH*NCAPS*ODIM];
__device__ float g_sR[NREP*BATCH*NCAPS*ODIM];

__device__ __forceinline__ u64 pack2(float x){u64 r;asm("mov.b64 %0,{%1,%1};":"=l"(r):"f"(x));return r;}
__device__ __forceinline__ u64 packpair(float a,float b){u64 r;asm("mov.b64 %0,{%1,%2};":"=l"(r):"f"(a),"f"(b));return r;}
__device__ __forceinline__ void ffma2(u64&d,u64 a,u64 b){asm("fma.rn.f32x2 %0,%1,%2,%0;":"+l"(d):"l"(a),"l"(b));}
__device__ __forceinline__ float2 unpack2(u64 a){float2 f;asm("mov.b64 {%0,%1},%2;":"=f"(f.x),"=f"(f.y):"l"(a));return f;}
__device__ __forceinline__ void cpasync16(u32 s,const void* g){asm volatile("cp.async.cg.shared.global [%0],[%1],16;"::"r"(s),"l"(g));}
__device__ __forceinline__ void cpcommit(){asm volatile("cp.async.commit_group;");}
__device__ __forceinline__ void cpwait0(){asm volatile("cp.async.wait_group 0;");}

__device__ __forceinline__ void ldsm_x4(u32& r0,u32& r1,u32& r2,u32& r3,u32 a){
    asm volatile("ldmatrix.sync.aligned.m8n8.x4.shared.b16 {%0,%1,%2,%3},[%4];"
        :"=r"(r0),"=r"(r1),"=r"(r2),"=r"(r3):"r"(a));
}
__device__ __forceinline__ void mma_bf16(float* d,const u32* a,u32 b0,u32 b1){
    asm volatile("mma.sync.aligned.m16n8k16.row.col.f32.bf16.bf16.f32 "
        "{%0,%1,%2,%3},{%4,%5,%6,%7},{%8,%9},{%0,%1,%2,%3};"
        :"+f"(d[0]),"+f"(d[1]),"+f"(d[2]),"+f"(d[3])
        :"r"(a[0]),"r"(a[1]),"r"(a[2]),"r"(a[3]),"r"(b0),"r"(b1));
}

// ============================================================
// one-time: conv2 weights -> bf16 hi/lo [ic][split][oc][96]
__global__ __launch_bounds__(256) void wbf_transform_kernel(const float* __restrict__ w)
{
    int idx = blockIdx.x*256 + threadIdx.x;
    if (idx >= 64*2*64*96) return;
    int ic = idx / 12288;
    int rem = idx - ic*12288;
    int s = rem / 6144;
    int oc = (rem / 96) & 63;
    int k = rem % 96;
    float val = (k < 81) ? w[(size_t)(oc*64+ic)*81 + k] : 0.f;
    __nv_bfloat16 hi = __float2bfloat16(val);
    g_wbf2[idx] = s ? __float2bfloat16(val - __bfloat162float(hi)) : hi;
}

// ============================================================
// conv1 (unchanged, f32x2)
__global__ __launch_bounds__(256) void conv1_kernel(
    const float* __restrict__ x, const float* __restrict__ w, const float* __restrict__ bias)
{
    __shared__ float xs[20][20];
    __shared__ u64 ws2[25*32];
    __shared__ float bs[64];
    int b = blockIdx.z, ty0 = blockIdx.y*16, tx0 = blockIdx.x*16;
    int tid = threadIdx.y*16 + threadIdx.x;
    for (int i = tid; i < 25*32; i += 256) {
        int k = i>>5, p = i&31;
        ws2[i] = packpair(w[(2*p)*25+k], w[(2*p+1)*25+k]);
    }
    if (tid < 64) bs[tid] = bias[tid];
    const float* xb = x + (size_t)b*HW1*HW1;
    for (int i = tid; i < 400; i += 256) {
        int r = i/20, c = i%20, gy = ty0+r-2, gx = tx0+c-2;
        float v = 0.f;
        if (gy>=0 && gy<HW1 && gx>=0 && gx<HW1) v = xb[gy*HW1+gx];
        xs[r][c] = v;
    }
    __syncthreads();
    int ty = threadIdx.y, tx = threadIdx.x;
    u64 in2[25];
#pragma unroll
    for (int kh = 0; kh < 5; kh++)
#pragma unroll
        for (int kw = 0; kw < 5; kw++) in2[kh*5+kw] = pack2(xs[ty+kh][tx+kw]);
    float* hout = g_h + ((size_t)b*64)*HW1*HW1 + (ty0+ty)*HW1 + tx0+tx;
#pragma unroll 4
    for (int p = 0; p < 32; p++) {
        u64 acc = packpair(bs[2*p], bs[2*p+1]);
#pragma unroll
        for (int k = 0; k < 25; k++) ffma2(acc, in2[k], ws2[k*32+p]);
        float2 f = unpack2(acc);
        hout[(size_t)(2*p)*HW1*HW1]   = fmaxf(f.x, 0.f);
        hout[(size_t)(2*p+1)*HW1*HW1] = fmaxf(f.y, 0.f);
    }
}

// ============================================================
// conv2 via mma.sync bf16 split-3; A=112 rows; B-frag reuse;
// conflict-free im2col (warp=pixels, lane=j); 2 CTAs/SM.
#define APITCH 208
#define A_HI 0
#define A_LO 23296
#define B_OFF 46592          // [buf][split][64][208B]
#define INS_OFF 99840        // [buf][15 x 68 floats]
#define INS_PITCH 68
#define TC_SMEM (108000 + 1024)

__global__ __launch_bounds__(256, 2) void conv2_mma_kernel(const float* __restrict__ bias)
{
    extern __shared__ char smraw[];
    char* sm = (char*)((((size_t)smraw) + 1023) & ~(size_t)1023);
    u32 smb = (u32)__cvta_generic_to_shared(sm);

    int tid = threadIdx.x, w = tid>>5, lane = tid&31;
    int b = blockIdx.y, t = blockIdx.x;

    // zero A hi+lo (k-pad cols 82..95 stay zero forever)
    for (int i = tid; i < 11648; i += 256) ((u32*)sm)[i] = 0;

    const float* insrc = g_h + (size_t)b*64*4096 + (size_t)(8*t)*64;

    auto stageB = [&](int ic, int buf) {
        const __nv_bfloat16* src = g_wbf2 + (size_t)ic*12288;
        u32 dstb = smb + B_OFF + buf*26624;
#pragma unroll
        for (int k = 0; k < 6; k++) {
            int i = tid + k*256;          // 0..1535
            int s = i / 768;
            int r = i - s*768;
            int n = r / 12, c = r - n*12;
            cpasync16(dstb + s*13312 + n*APITCH + c*16, src + (size_t)s*6144 + n*96 + c*8);
        }
    };
    auto stageI = [&](int ic, int buf) {
        if (tid < 240) {
            int r = tid >> 4, c = tid & 15;
            cpasync16(smb + INS_OFF + buf*4080 + r*(INS_PITCH*4) + c*16,
                      insrc + (size_t)ic*4096 + tid*4);
        }
    };

    float acc[8][4];
#pragma unroll
    for (int nt = 0; nt < 8; nt++)
#pragma unroll
        for (int k = 0; k < 4; k++) acc[nt][k] = 0.f;

    stageB(0, 0); stageI(0, 0); cpcommit();

    // ldmatrix lane addresses (fixed parts)
    u32 a_row  = (u32)(w*16 + (lane & 15));
    u32 a_kofs = (u32)((lane >> 4) * 8);
    u32 b_nrow = (u32)((lane & 7) + (lane >> 4)*8);
    u32 b_kofs = (u32)(((lane >> 3) & 1) * 8);

    for (int ic = 0; ic < 64; ic++) {
        int cur = ic & 1;
        cpwait0();
        __syncthreads();                 // staged(cur) ready; prev mma done

        // im2col A hi/lo: warp w owns pixels w*14..w*14+13, lane = j
        {
            const float* insf = (const float*)(sm + INS_OFF + cur*4080);
            int p0 = w*14;
#pragma unroll 2
            for (int pi = 0; pi < 14; pi++) {
                int p = p0 + pi;
                int pr = (p*2341) >> 16;         // p/28
                int inb = pr*(2*INS_PITCH) + 2*(p - pr*28);
#pragma unroll
                for (int half = 0; half < 2; half++) {
                    int j = lane + half*32;
                    if (j > 40) break;
                    int q0 = 2*j, q1 = q0+1;
                    int kh0 = (q0*456)>>12, kw0 = q0 - kh0*9;
                    float v0 = insf[inb + kh0*INS_PITCH + kw0];
                    float v1 = 0.f;
                    if (q1 <= 80) {
                        int kh1 = (q1*456)>>12, kw1 = q1 - kh1*9;
                        v1 = insf[inb + kh1*INS_PITCH + kw1];
                    }
                    __nv_bfloat16 h0 = __float2bfloat16(v0), h1 = __float2bfloat16(v1);
                    __nv_bfloat16 l0 = __float2bfloat16(v0 - __bfloat162float(h0));
                    __nv_bfloat16 l1 = __float2bfloat16(v1 - __bfloat162float(h1));
                    u32 whi = (u32)__bfloat16_as_ushort(h0) | ((u32)__bfloat16_as_ushort(h1)<<16);
                    u32 wlo = (u32)__bfloat16_as_ushort(l0) | ((u32)__bfloat16_as_ushort(l1)<<16);
                    int off = p*APITCH + j*4;
                    *(u32*)(sm + A_HI + off) = whi;
                    *(u32*)(sm + A_LO + off) = wlo;
                }
            }
        }
        if (ic < 63) { stageB(ic+1, cur^1); stageI(ic+1, cur^1); cpcommit(); }
        __syncthreads();                 // A ready

        if (w < 7) {
            u32 bbase = smb + B_OFF + cur*26624;
#pragma unroll
            for (int ks = 0; ks < 6; ks++) {
                u32 k0 = ks*16;
                u32 ah[4], al[4];
                ldsm_x4(ah[0], ah[1], ah[2], ah[3], smb + A_HI + a_row*APITCH + (k0 + a_kofs)*2);
                ldsm_x4(al[0], al[1], al[2], al[3], smb + A_LO + a_row*APITCH + (k0 + a_kofs)*2);
#pragma unroll
                for (int ntp = 0; ntp < 4; ntp++) {
                    u32 brow = (ntp*16 + b_nrow)*APITCH + (k0 + b_kofs)*2;
                    u32 bh[4], bl[4];
                    ldsm_x4(bh[0], bh[1], bh[2], bh[3], bbase + brow);
                    ldsm_x4(bl[0], bl[1], bl[2], bl[3], bbase + 13312 + brow);
                    mma_bf16(acc[2*ntp],   ah, bh[0], bh[1]);
                    mma_bf16(acc[2*ntp+1], ah, bh[2], bh[3]);
                    mma_bf16(acc[2*ntp],   al, bh[0], bh[1]);
                    mma_bf16(acc[2*ntp+1], al, bh[2], bh[3]);
                    mma_bf16(acc[2*ntp],   ah, bl[0], bl[1]);
                    mma_bf16(acc[2*ntp+1], ah, bl[2], bl[3]);
                }
            }
        }
    }

    // epilogue: lane holds cols (lane%4)*2,+1 of each n-tile, rows w*16+l/4 and +8
    if (w < 7) {
        int c2 = (lane & 3)*2;
        float b0v[8], b1v[8];
#pragma unroll
        for (int nt = 0; nt < 8; nt++) { b0v[nt] = bias[nt*8 + c2]; b1v[nt] = bias[nt*8 + c2 + 1]; }
#pragma unroll
        for (int rr = 0; rr < 2; rr++) {
            int pp = w*16 + (lane >> 2) + rr*8;
            int n_base = 112*t + pp;
#pragma unroll
            for (int nt = 0; nt < 8; nt++) {
                float a0 = acc[nt][rr*2]   + b0v[nt];
                float a1 = acc[nt][rr*2+1] + b1v[nt];
                float part = a0*a0 + a1*a1;
                part += __shfl_xor_sync(0xffffffff, part, 1);
                part += __shfl_xor_sync(0xffffffff, part, 2);
                float mag = sqrtf(part + EPS);
                float scale = part/(1.f+part)/(mag+EPS);
                float* up = g_u + ((size_t)(nt*784 + n_base)*BATCH + b)*JDIM + c2;
                *(float2*)up = make_float2(a0*scale, a1*scale);
            }
        }
    }
}

// ============================================================
// routing sweep (unchanged from 889us build)
#define R_WS  (NPER*1280)
#define R_USA (NPER*32*4)
#define R_USB (NPER*32*4)
#define R_EX  (2*NCAPS*32)
#define R_SMEM ((R_WS + R_USA + R_USB + R_EX)*4)

__global__ __launch_bounds__(320, 2) void route_kernel(const float* __restrict__ W, int iter)
{
    extern __shared__ float dsm[];
    float* Ws  = dsm;
    float* usA = dsm + R_WS;
    float* usB = dsm + R_WS + R_USA;
    float* ex  = dsm + R_WS + R_USA + R_USB;

    int tid = threadIdx.x, o = tid>>5, lane = tid&31;
    int h = blockIdx.y, bb = h*32 + lane;
    int n0 = blockIdx.x * NPER;

    u32 s_ws  = (u32)__cvta_generic_to_shared(Ws);
    u32 s_usA = (u32)__cvta_generic_to_shared(usA);
    u32 s_usB = (u32)__cvta_generic_to_shared(usB);

    const float* wsrc = W + (size_t)n0*1280;
#pragma unroll
    for (int k = 0; k < 16; k++) {
        int i = tid + k*320;
        cpasync16(s_ws + i*16, wsrc + (size_t)i*4);
    }
#pragma unroll
    for (int k = 0; k < 4; k++) {
        int i = tid + k*320;
        if (i < 1024) {
            int nn = i>>6, rem = i&63, half = rem>>5, ll = rem&31;
            u32 dst = (half ? s_usB : s_usA) + (nn*32 + ll)*16;
            cpasync16(dst, g_u + ((size_t)(n0+nn)*BATCH + h*32 + ll)*JDIM + half*4);
        }
    }
    cpcommit();

    float v[16];
    if (iter > 0) {
        const float4* vp = (const float4*)(g_v + (bb*NCAPS + o)*ODIM);
#pragma unroll
        for (int k = 0; k < 4; k++) {
            float4 f = vp[k];
            v[4*k]=f.x; v[4*k+1]=f.y; v[4*k+2]=f.z; v[4*k+3]=f.w;
        }
    }
    float acc[16];
#pragma unroll
    for (int i = 0; i < 16; i++) acc[i] = 0.f;

    cpwait0();
    __syncthreads();

    for (int nn = 0; nn < NPER; nn++) {
        float4 ua = ((const float4*)usA)[nn*32 + lane];
        float4 ub = ((const float4*)usB)[nn*32 + lane];
        float uh[16];
        const float* wrow = Ws + nn*1280 + o*128;
#pragma unroll
        for (int i = 0; i < 16; i++) {
            float4 wa = *(const float4*)(wrow + i*8);
            float4 wb = *(const float4*)(wrow + i*8 + 4);
            float s = wa.x*ua.x;
            s = fmaf(wa.y,ua.y,s); s = fmaf(wa.z,ua.z,s); s = fmaf(wa.w,ua.w,s);
            s = fmaf(wb.x,ub.x,s); s = fmaf(wb.y,ub.y,s);
            s = fmaf(wb.z,ub.z,s); s = fmaf(wb.w,ub.w,s);
            uh[i] = s;
        }
        float c;
        if (iter == 0) c = 0.1f;
        else {
            float bnew = 0.f;
#pragma unroll
            for (int i = 0; i < 16; i++) bnew = fmaf(uh[i], v[i], bnew);
            float e = __expf(bnew);
            int par = nn & 1;
            ex[(par*NCAPS + o)*32 + lane] = e;
            __syncthreads();
            float denom = 0.f;
#pragma unroll
            for (int k = 0; k < 10; k++) denom += ex[(par*NCAPS + k)*32 + lane];
            c = __fdividef(e, denom);
        }
#pragma unroll
        for (int i = 0; i < 16; i++) acc[i] = fmaf(c, uh[i], acc[i]);
    }
    int rep = (blockIdx.x*2 + blockIdx.y) & (NREP-1);
    float* sp = g_sR + rep*(BATCH*NCAPS*ODIM) + (bb*NCAPS + o)*ODIM;
#pragma unroll
    for (int i = 0; i < 16; i++) atomicAdd(&sp[i], acc[i]);
}

// ============================================================
__global__ __launch_bounds__(256) void squash_v_kernel(float* __restrict__ out, int mode)
{
    int tid = blockIdx.x*256 + threadIdx.x;
    int boq = tid>>2, quad = tid&3;
    float4 s = make_float4(0.f,0.f,0.f,0.f);
#pragma unroll
    for (int r = 0; r < NREP; r++) {
        float* p = g_sR + r*(BATCH*NCAPS*ODIM) + boq*ODIM + quad*4;
        float4 t = *(const float4*)p;
        *(float4*)p = make_float4(0.f,0.f,0.f,0.f);
        s.x += t.x; s.y += t.y; s.z += t.z; s.w += t.w;
    }
    float part = s.x*s.x + s.y*s.y + s.z*s.z + s.w*s.w;
    part += __shfl_xor_sync(0xffffffff, part, 1);
    part += __shfl_xor_sync(0xffffffff, part, 2);
    float msq = part;
    float mag = sqrtf(msq + EPS);
    float scale = msq/(1.f+msq)/(mag+EPS);
    float4 vv = make_float4(s.x*scale, s.y*scale, s.z*scale, s.w*scale);
    if (mode == 0) *(float4*)(g_v + boq*ODIM + quad*4) = vv;
    else if (mode == 1) {
        float4 old = *(const float4*)(g_v + boq*ODIM + quad*4);
        old.x += vv.x; old.y += vv.y; old.z += vv.z; old.w += vv.w;
        *(float4*)(g_v + boq*ODIM + quad*4) = old;
    } else *(float4*)(out + boq*ODIM + quad*4) = vv;
}

// ============================================================
extern "C" void kernel_launch(void* const* d_in, const int* in_sizes, int n_in,
                              void* d_out, int out_size)
{
    const float* x   = (const float*)d_in[0];
    const float* c1w = (const float*)d_in[1];
    const float* c1b = (const float*)d_in[2];
    const float* pw  = (const float*)d_in[3];
    const float* pb  = (const float*)d_in[4];
    const float* W   = (const float*)d_in[5];
    float* out = (float*)d_out;

    static int attr_done = 0;
    if (!attr_done) {
        cudaFuncSetAttribute(conv2_mma_kernel, cudaFuncAttributeMaxDynamicSharedMemorySize, TC_SMEM);
        cudaFuncSetAttribute(route_kernel, cudaFuncAttributeMaxDynamicSharedMemorySize, R_SMEM);
        attr_done = 1;
    }

    wbf_transform_kernel<<<(64*2*64*96 + 255)/256, 256>>>(pw);
    conv1_kernel<<<dim3(4,4,64), dim3(16,16)>>>(x, c1w, c1b);
    conv2_mma_kernel<<<dim3(7,64), 256, TC_SMEM>>>(pb);

    route_kernel<<<dim3(RBLOCKS,2), 320, R_SMEM>>>(W, 0);
    squash_v_kernel<<<10, 256>>>(out, 0);
    route_kernel<<<dim3(RBLOCKS,2), 320, R_SMEM>>>(W, 1);
    squash_v_kernel<<<10, 256>>>(out, 1);
    route_kernel<<<dim3(RBLOCKS,2), 320, R_SMEM>>>(W, 2);
    squash_v_kernel<<<10, 256>>>(out, 2);
}